// round 8
// baseline (speedup 1.0000x reference)
#include <cuda_runtime.h>

// Shapes (fixed):
//   batch:          int32  [E, NT]          = 300000 elems
//   batch_features: fp32   [N, D]           = 6400000 elems
//   att_weights:    fp32   [NT*E, H, NT-1]  = 2400000 elems
//   out:            fp32   [N, H*D]         = 25600000 elems
static constexpr int   E     = 100000;
static constexpr int   N     = 50000;
static constexpr int   H     = 4;
static constexpr int   D     = 128;
static constexpr int   NT    = 3;
static constexpr int   NE    = NT * E;      // 300000 entries
static constexpr int   CAP   = 64;          // bucket capacity (Poisson(6) max ~25)
static constexpr float ALPHA = 0.2f;

// ---- scratch (__device__ globals; allocation-free rule) ----
// g_cursor is zero-initialized at module load (CUDA guarantee) and k_main
// self-cleans it back to zero every call, so no zeroing kernel is needed.
__device__ int  g_cursor[N];
__device__ int4 g_bucket[(size_t)N * CAP];  // {n0, n1, ei, pad}, 51.2 MB

// ---------------------------------------------------------------------------
// K1: scatter. One thread per event e emits all NT=3 entries.
//   entry (e, i): node = batch[e][i], gathers the two other columns,
//   weight row ei = i*E + e  (matches jnp.concatenate block order).
// ---------------------------------------------------------------------------
__global__ void k_fill(const int* __restrict__ batch) {
    int e = blockIdx.x * blockDim.x + threadIdx.x;
    if (e >= E) return;

    int b0 = __ldg(&batch[e * NT + 0]);
    int b1 = __ldg(&batch[e * NT + 1]);
    int b2 = __ldg(&batch[e * NT + 2]);

    int s0 = atomicAdd(&g_cursor[b0], 1);
    if (s0 < CAP) g_bucket[(size_t)b0 * CAP + s0] = make_int4(b1, b2, e, 0);

    int s1 = atomicAdd(&g_cursor[b1], 1);
    if (s1 < CAP) g_bucket[(size_t)b1 * CAP + s1] = make_int4(b0, b2, E + e, 0);

    int s2 = atomicAdd(&g_cursor[b2], 1);
    if (s2 < CAP) g_bucket[(size_t)b2 * CAP + s2] = make_int4(b0, b1, 2 * E + e, 0);
}

// ---------------------------------------------------------------------------
// K2: main. One warp per node; lane owns d in [4*lane, 4*lane+4).
// Entry metadata loaded once per warp (coalesced; lane q holds entry q),
// distributed via __shfl. Entries processed in PAIRS with a pair-ahead
// software pipeline => 4 feature-row loads in flight (MLP=4). Tails are
// padded by clamping the entry index — max is idempotent, so duplicated
// entries are harmless and the inner loop has no per-entry guards.
// ---------------------------------------------------------------------------
struct Ld { float4 f0, f1, wa, wb; };

__device__ __forceinline__ Ld issue_entry(int q, int cnt, const int4& myent,
                                          size_t base, int lane,
                                          const float4* __restrict__ bf4,
                                          const float4* __restrict__ aw4) {
    int qc = min(q, cnt - 1);          // clamp: duplicates are no-ops under max
    int n0, n1, ei;
    if (qc < 32) {
        n0 = __shfl_sync(0xffffffffu, myent.x, qc);
        n1 = __shfl_sync(0xffffffffu, myent.y, qc);
        ei = __shfl_sync(0xffffffffu, myent.z, qc);
    } else {                           // cnt > 32: effectively never
        int4 t = g_bucket[base + qc];
        n0 = t.x; n1 = t.y; ei = t.z;
    }
    Ld r;
    r.f0 = __ldg(&bf4[n0 * (D / 4) + lane]);
    r.f1 = __ldg(&bf4[n1 * (D / 4) + lane]);
    r.wa = __ldg(&aw4[ei * 2 + 0]);    // {w00,w01,w10,w11}
    r.wb = __ldg(&aw4[ei * 2 + 1]);    // {w20,w21,w30,w31}
    return r;
}

__device__ __forceinline__ void accum(const Ld& L, float4 (&m)[H]) {
    float w00 = L.wa.x, w01 = L.wa.y, w10 = L.wa.z, w11 = L.wa.w;
    float w20 = L.wb.x, w21 = L.wb.y, w30 = L.wb.z, w31 = L.wb.w;
    const float4 f0 = L.f0, f1 = L.f1;

    m[0].x = fmaxf(m[0].x, fmaf(w00, f0.x, w01 * f1.x));
    m[0].y = fmaxf(m[0].y, fmaf(w00, f0.y, w01 * f1.y));
    m[0].z = fmaxf(m[0].z, fmaf(w00, f0.z, w01 * f1.z));
    m[0].w = fmaxf(m[0].w, fmaf(w00, f0.w, w01 * f1.w));

    m[1].x = fmaxf(m[1].x, fmaf(w10, f0.x, w11 * f1.x));
    m[1].y = fmaxf(m[1].y, fmaf(w10, f0.y, w11 * f1.y));
    m[1].z = fmaxf(m[1].z, fmaf(w10, f0.z, w11 * f1.z));
    m[1].w = fmaxf(m[1].w, fmaf(w10, f0.w, w11 * f1.w));

    m[2].x = fmaxf(m[2].x, fmaf(w20, f0.x, w21 * f1.x));
    m[2].y = fmaxf(m[2].y, fmaf(w20, f0.y, w21 * f1.y));
    m[2].z = fmaxf(m[2].z, fmaf(w20, f0.z, w21 * f1.z));
    m[2].w = fmaxf(m[2].w, fmaf(w20, f0.w, w21 * f1.w));

    m[3].x = fmaxf(m[3].x, fmaf(w30, f0.x, w31 * f1.x));
    m[3].y = fmaxf(m[3].y, fmaf(w30, f0.y, w31 * f1.y));
    m[3].z = fmaxf(m[3].z, fmaf(w30, f0.z, w31 * f1.z));
    m[3].w = fmaxf(m[3].w, fmaf(w30, f0.w, w31 * f1.w));
}

__global__ __launch_bounds__(256)
void k_main(const float* __restrict__ bf,
            const float* __restrict__ aw,
            float*       __restrict__ out) {
    const int warp = (blockIdx.x * blockDim.x + threadIdx.x) >> 5;
    const int lane = threadIdx.x & 31;
    if (warp >= N) return;
    const int n = warp;

    const float4* __restrict__ bf4  = reinterpret_cast<const float4*>(bf);
    const float4* __restrict__ aw4  = reinterpret_cast<const float4*>(aw);
    float4*       __restrict__ out4 = reinterpret_cast<float4*>(out);

    const int cnt = min(g_cursor[n], CAP);     // >= 1 guaranteed by reference
    if (lane == 0) g_cursor[n] = 0;            // self-clean for next replay
    const size_t base = (size_t)n * CAP;

    // lane q caches entry q's metadata (one coalesced 16B load)
    int4 myent = g_bucket[base + min(lane, cnt - 1)];

    const float NEG_INF = __int_as_float(0xff800000);
    float4 m[H];
#pragma unroll
    for (int h = 0; h < H; h++)
        m[h] = make_float4(NEG_INF, NEG_INF, NEG_INF, NEG_INF);

    // prologue: pair 0
    Ld A0 = issue_entry(0, cnt, myent, base, lane, bf4, aw4);
    Ld A1 = issue_entry(1, cnt, myent, base, lane, bf4, aw4);

    for (int q = 0; q < cnt; q += 2) {
        Ld B0, B1;
        const bool more = (q + 2) < cnt;
        if (more) {                            // prefetch next pair (MLP=4)
            B0 = issue_entry(q + 2, cnt, myent, base, lane, bf4, aw4);
            B1 = issue_entry(q + 3, cnt, myent, base, lane, bf4, aw4);
        }
        accum(A0, m);
        accum(A1, m);                          // may duplicate A0 at tail: harmless
        if (more) { A0 = B0; A1 = B1; }
    }

    // epilogue: out[n, h*D + d] = leaky_relu(bf[n, d] + max)
    float4 bse = __ldg(&bf4[n * (D / 4) + lane]);
#pragma unroll
    for (int h = 0; h < H; h++) {
        float4 o;
        o.x = bse.x + m[h].x;
        o.y = bse.y + m[h].y;
        o.z = bse.z + m[h].z;
        o.w = bse.w + m[h].w;
        // leaky_relu(x) == max(x, alpha*x) for 0 < alpha < 1
        o.x = fmaxf(o.x, ALPHA * o.x);
        o.y = fmaxf(o.y, ALPHA * o.y);
        o.z = fmaxf(o.z, ALPHA * o.z);
        o.w = fmaxf(o.w, ALPHA * o.w);
        // streaming store: don't evict the L2-resident feature table
        __stcs(&out4[n * (H * D / 4) + h * (D / 4) + lane], o);
    }
}

// ---------------------------------------------------------------------------
extern "C" void kernel_launch(void* const* d_in, const int* in_sizes, int n_in,
                              void* d_out, int out_size) {
    const int*   batch = nullptr;
    const float* bf    = nullptr;
    const float* aw    = nullptr;
    for (int i = 0; i < n_in; i++) {
        if (in_sizes[i] == E * NT)                 batch = (const int*)d_in[i];
        else if (in_sizes[i] == N * D)             bf    = (const float*)d_in[i];
        else if (in_sizes[i] == NE * H * (NT - 1)) aw    = (const float*)d_in[i];
    }
    float* out = (float*)d_out;

    k_fill<<<(E + 255) / 256, 256>>>(batch);
    k_main<<<(N + 7) / 8, 256>>>(bf, aw, out);
}